// round 3
// baseline (speedup 1.0000x reference)
#include <cuda_runtime.h>

#define B_  8
#define N_  1024
#define C_  1024
#define H_  16
#define HD_ 64
#define QKV_COLS (3 * C_)   // 3072

// Scratch (allocation-free: device globals)
__device__ float g_qkv[(size_t)B_ * N_ * QKV_COLS];  // [B*N, 3072]
__device__ float g_ao [(size_t)B_ * N_ * C_];        // [B*N, 1024] (b,n,h,hd)

// ---------------------------------------------------------------------------
// NT SGEMM: C[M,Nn] = A[M,K] @ B[Nn,K]^T (+ bias[Nn])
// 128x128 tile, BK=16, 256 threads, 8x8 per-thread fragments.
// ---------------------------------------------------------------------------
template <bool BIAS>
__global__ __launch_bounds__(256)
void sgemm_nt(const float* __restrict__ A, const float* __restrict__ Bm,
              const float* __restrict__ bias, float* __restrict__ Cc,
              int M, int Nn, int K)
{
    __shared__ float As[16][132];
    __shared__ float Bs[16][132];

    const int tid = threadIdx.x;
    const int tx = tid & 15;          // 0..15 -> col group
    const int ty = tid >> 4;          // 0..15 -> row group
    const int m0 = blockIdx.y * 128;
    const int n0 = blockIdx.x * 128;

    float acc[8][8];
#pragma unroll
    for (int i = 0; i < 8; ++i)
#pragma unroll
        for (int j = 0; j < 8; ++j) acc[i][j] = 0.f;

    for (int kt = 0; kt < K; kt += 16) {
#pragma unroll
        for (int it = 0; it < 2; ++it) {
            int e   = tid + it * 256;        // 0..511
            int row = e >> 2;                // 0..127
            int kc  = (e & 3) << 2;          // 0,4,8,12
            float4 va = *(const float4*)(A  + (size_t)(m0 + row) * K + kt + kc);
            As[kc + 0][row] = va.x; As[kc + 1][row] = va.y;
            As[kc + 2][row] = va.z; As[kc + 3][row] = va.w;
            float4 vb = *(const float4*)(Bm + (size_t)(n0 + row) * K + kt + kc);
            Bs[kc + 0][row] = vb.x; Bs[kc + 1][row] = vb.y;
            Bs[kc + 2][row] = vb.z; Bs[kc + 3][row] = vb.w;
        }
        __syncthreads();

#pragma unroll
        for (int k = 0; k < 16; ++k) {
            float a[8], b[8];
            *(float4*)(a)     = *(const float4*)&As[k][ty * 8];
            *(float4*)(a + 4) = *(const float4*)&As[k][ty * 8 + 4];
            *(float4*)(b)     = *(const float4*)&Bs[k][tx * 8];
            *(float4*)(b + 4) = *(const float4*)&Bs[k][tx * 8 + 4];
#pragma unroll
            for (int i = 0; i < 8; ++i)
#pragma unroll
                for (int j = 0; j < 8; ++j)
                    acc[i][j] = fmaf(a[i], b[j], acc[i][j]);
        }
        __syncthreads();
    }

#pragma unroll
    for (int i = 0; i < 8; ++i) {
        float* crow = Cc + (size_t)(m0 + ty * 8 + i) * Nn + n0 + tx * 8;
#pragma unroll
        for (int j = 0; j < 8; ++j) {
            float v = acc[i][j];
            if (BIAS) v += bias[n0 + tx * 8 + j];
            crow[j] = v;
        }
    }
}

// ---------------------------------------------------------------------------
// Flash attention: one block = (b,h) x 64-query tile, loops 16 key tiles of 64.
// Dynamic smem: Qs[64][68] (d-major, pre-scaled), Ks[64][68] (d-major),
//               Vs[64][64] (m-major), Ps[64][68] (P staging for P@V).
// ---------------------------------------------------------------------------
#define QSS 68
#define ATTN_SMEM_FLOATS (64 * QSS * 3 + 64 * 64)
#define ATTN_SMEM_BYTES  (ATTN_SMEM_FLOATS * 4)

__global__ __launch_bounds__(256)
void attn_kernel(const float* __restrict__ qkv, float* __restrict__ ao)
{
    extern __shared__ float sm[];
    float* Qs = sm;
    float* Ks = sm + 64 * QSS;
    float* Vs = sm + 2 * 64 * QSS;
    float* Ps = sm + 2 * 64 * QSS + 64 * 64;

    const int tid = threadIdx.x;
    const int tx = tid & 15;      // key-col / d-col group (4 wide)
    const int ty = tid >> 4;      // query-row group (4 wide)
    const int bh = blockIdx.x;
    const int b  = bh >> 4;
    const int h  = bh & 15;
    const int r0 = blockIdx.y * 64;
    const float scale = 0.125f;   // HD^-0.5

    const float* qb = qkv + (size_t)b * N_ * QKV_COLS + h * HD_;

    // Load Q tile transposed (Qs[d][r]), pre-scaled
#pragma unroll
    for (int it = 0; it < 4; ++it) {
        int e = tid + it * 256;          // 0..1023
        int r = e >> 4;                  // 0..63
        int d = (e & 15) << 2;           // 0..60
        float4 v = *(const float4*)(qb + (size_t)(r0 + r) * QKV_COLS + d);
        Qs[(d + 0) * QSS + r] = v.x * scale;
        Qs[(d + 1) * QSS + r] = v.y * scale;
        Qs[(d + 2) * QSS + r] = v.z * scale;
        Qs[(d + 3) * QSS + r] = v.w * scale;
    }

    float mrow[4], lrow[4], o[4][4];
#pragma unroll
    for (int i = 0; i < 4; ++i) {
        mrow[i] = -1e30f; lrow[i] = 0.f;
#pragma unroll
        for (int j = 0; j < 4; ++j) o[i][j] = 0.f;
    }

    for (int t = 0; t < 16; ++t) {
        __syncthreads();   // previous P@V done before overwriting K/V/P tiles

        // Load K (transposed, d-major) and V (m-major) tiles
#pragma unroll
        for (int it = 0; it < 4; ++it) {
            int e = tid + it * 256;
            int m = e >> 4;
            int d = (e & 15) << 2;
            const float* kb = qkv + (size_t)(b * N_ + t * 64 + m) * QKV_COLS
                              + C_ + h * HD_ + d;
            float4 kv = *(const float4*)kb;
            Ks[(d + 0) * QSS + m] = kv.x;
            Ks[(d + 1) * QSS + m] = kv.y;
            Ks[(d + 2) * QSS + m] = kv.z;
            Ks[(d + 3) * QSS + m] = kv.w;
            float4 vv = *(const float4*)(kb + C_);
            *(float4*)&Vs[m * 64 + d] = vv;
        }
        __syncthreads();

        // S = (Q*scale) @ K^T, 4x4 fragment per thread
        float s[4][4];
#pragma unroll
        for (int i = 0; i < 4; ++i)
#pragma unroll
            for (int j = 0; j < 4; ++j) s[i][j] = 0.f;

#pragma unroll 8
        for (int d = 0; d < 64; ++d) {
            float a[4], bb[4];
            *(float4*)a  = *(const float4*)&Qs[d * QSS + ty * 4];
            *(float4*)bb = *(const float4*)&Ks[d * QSS + tx * 4];
#pragma unroll
            for (int i = 0; i < 4; ++i)
#pragma unroll
                for (int j = 0; j < 4; ++j)
                    s[i][j] = fmaf(a[i], bb[j], s[i][j]);
        }

        // Online softmax (row stats reduced across the 16 tx lanes)
#pragma unroll
        for (int i = 0; i < 4; ++i) {
            float rm = fmaxf(fmaxf(s[i][0], s[i][1]), fmaxf(s[i][2], s[i][3]));
#pragma unroll
            for (int off = 8; off >= 1; off >>= 1)
                rm = fmaxf(rm, __shfl_xor_sync(0xffffffffu, rm, off));
            float mnew  = fmaxf(mrow[i], rm);
            float alpha = __expf(mrow[i] - mnew);
            float rs = 0.f;
#pragma unroll
            for (int j = 0; j < 4; ++j) {
                s[i][j] = __expf(s[i][j] - mnew);
                rs += s[i][j];
            }
#pragma unroll
            for (int off = 8; off >= 1; off >>= 1)
                rs += __shfl_xor_sync(0xffffffffu, rs, off);
            lrow[i] = lrow[i] * alpha + rs;
            mrow[i] = mnew;
#pragma unroll
            for (int j = 0; j < 4; ++j) o[i][j] *= alpha;
            *(float4*)&Ps[(ty * 4 + i) * QSS + tx * 4] =
                make_float4(s[i][0], s[i][1], s[i][2], s[i][3]);
        }
        __syncthreads();

        // O += P @ V  (o fragment cols are d-cols tx*4..+3)
#pragma unroll 8
        for (int m = 0; m < 64; ++m) {
            float bb[4];
            *(float4*)bb = *(const float4*)&Vs[m * 64 + tx * 4];
#pragma unroll
            for (int i = 0; i < 4; ++i) {
                float av = Ps[(ty * 4 + i) * QSS + m];
#pragma unroll
                for (int j = 0; j < 4; ++j)
                    o[i][j] = fmaf(av, bb[j], o[i][j]);
            }
        }
    }

    // Epilogue: O / l -> [b, n, h, hd] layout for out-proj
#pragma unroll
    for (int i = 0; i < 4; ++i) {
        float inv = 1.f / lrow[i];
        int r = r0 + ty * 4 + i;
        float4 v = make_float4(o[i][0] * inv, o[i][1] * inv,
                               o[i][2] * inv, o[i][3] * inv);
        *(float4*)(ao + (size_t)(b * N_ + r) * C_ + h * HD_ + tx * 4) = v;
    }
}

// ---------------------------------------------------------------------------
extern "C" void kernel_launch(void* const* d_in, const int* in_sizes, int n_in,
                              void* d_out, int out_size)
{
    const float* x      = (const float*)d_in[0];
    const float* w_qkv  = (const float*)d_in[1];
    const float* w_proj = (const float*)d_in[2];
    const float* b_proj = (const float*)d_in[3];
    float* out = (float*)d_out;

    float *qkv, *ao;
    cudaGetSymbolAddress((void**)&qkv, g_qkv);
    cudaGetSymbolAddress((void**)&ao,  g_ao);

    // 1) QKV projection: [8192,1024] @ [3072,1024]^T
    sgemm_nt<false><<<dim3(QKV_COLS / 128, (B_ * N_) / 128), 256>>>(
        x, w_qkv, nullptr, qkv, B_ * N_, QKV_COLS, C_);

    // 2) Flash attention
    cudaFuncSetAttribute(attn_kernel,
                         cudaFuncAttributeMaxDynamicSharedMemorySize,
                         ATTN_SMEM_BYTES);
    attn_kernel<<<dim3(B_ * H_, N_ / 64), 256, ATTN_SMEM_BYTES>>>(qkv, ao);

    // 3) Output projection + bias: [8192,1024] @ [1024,1024]^T + b
    sgemm_nt<true><<<dim3(C_ / 128, (B_ * N_) / 128), 256>>>(
        ao, w_proj, b_proj, out, B_ * N_, C_, C_);
}

// round 4
// speedup vs baseline: 1.0007x; 1.0007x over previous
#include <cuda_runtime.h>

#define B_  8
#define N_  1024
#define C_  1024
#define H_  16
#define HD_ 64
#define QKV_COLS (3 * C_)   // 3072

// Scratch (allocation-free: device globals)
__device__ float g_qkv[(size_t)B_ * N_ * QKV_COLS];  // [B*N, 3072]
__device__ float g_ao [(size_t)B_ * N_ * C_];        // [B*N, 1024] (b,n,h,hd)

// ---------------------------------------------------------------------------
// NT SGEMM: C[M,Nn] = A[M,K] @ B[Nn,K]^T (+ bias[Nn])
// 128x128 tile, BK=16, 256 threads, 8x8 per-thread fragments.
// ---------------------------------------------------------------------------
template <bool BIAS>
__global__ __launch_bounds__(256)
void sgemm_nt(const float* __restrict__ A, const float* __restrict__ Bm,
              const float* __restrict__ bias, float* __restrict__ Cc,
              int M, int Nn, int K)
{
    __shared__ float As[16][132];
    __shared__ float Bs[16][132];

    const int tid = threadIdx.x;
    const int tx = tid & 15;          // 0..15 -> col group
    const int ty = tid >> 4;          // 0..15 -> row group
    const int m0 = blockIdx.y * 128;
    const int n0 = blockIdx.x * 128;

    float acc[8][8];
#pragma unroll
    for (int i = 0; i < 8; ++i)
#pragma unroll
        for (int j = 0; j < 8; ++j) acc[i][j] = 0.f;

    for (int kt = 0; kt < K; kt += 16) {
#pragma unroll
        for (int it = 0; it < 2; ++it) {
            int e   = tid + it * 256;        // 0..511
            int row = e >> 2;                // 0..127
            int kc  = (e & 3) << 2;          // 0,4,8,12
            float4 va = *(const float4*)(A  + (size_t)(m0 + row) * K + kt + kc);
            As[kc + 0][row] = va.x; As[kc + 1][row] = va.y;
            As[kc + 2][row] = va.z; As[kc + 3][row] = va.w;
            float4 vb = *(const float4*)(Bm + (size_t)(n0 + row) * K + kt + kc);
            Bs[kc + 0][row] = vb.x; Bs[kc + 1][row] = vb.y;
            Bs[kc + 2][row] = vb.z; Bs[kc + 3][row] = vb.w;
        }
        __syncthreads();

#pragma unroll
        for (int k = 0; k < 16; ++k) {
            float a[8], b[8];
            *(float4*)(a)     = *(const float4*)&As[k][ty * 8];
            *(float4*)(a + 4) = *(const float4*)&As[k][ty * 8 + 4];
            *(float4*)(b)     = *(const float4*)&Bs[k][tx * 8];
            *(float4*)(b + 4) = *(const float4*)&Bs[k][tx * 8 + 4];
#pragma unroll
            for (int i = 0; i < 8; ++i)
#pragma unroll
                for (int j = 0; j < 8; ++j)
                    acc[i][j] = fmaf(a[i], b[j], acc[i][j]);
        }
        __syncthreads();
    }

#pragma unroll
    for (int i = 0; i < 8; ++i) {
        float* crow = Cc + (size_t)(m0 + ty * 8 + i) * Nn + n0 + tx * 8;
#pragma unroll
        for (int j = 0; j < 8; ++j) {
            float v = acc[i][j];
            if (BIAS) v += bias[n0 + tx * 8 + j];
            crow[j] = v;
        }
    }
}

// ---------------------------------------------------------------------------
// Flash attention: one block = (b,h) x 64-query tile, loops 16 key tiles of 64.
// Dynamic smem: Qs[64][68] (d-major, pre-scaled), Ks[64][68] (d-major),
//               Vs[64][64] (m-major), Ps[64][68] (P staging for P@V).
// ---------------------------------------------------------------------------
#define QSS 68
#define ATTN_SMEM_FLOATS (64 * QSS * 3 + 64 * 64)
#define ATTN_SMEM_BYTES  (ATTN_SMEM_FLOATS * 4)

__global__ __launch_bounds__(256)
void attn_kernel(const float* __restrict__ qkv, float* __restrict__ ao)
{
    extern __shared__ float sm[];
    float* Qs = sm;
    float* Ks = sm + 64 * QSS;
    float* Vs = sm + 2 * 64 * QSS;
    float* Ps = sm + 2 * 64 * QSS + 64 * 64;

    const int tid = threadIdx.x;
    const int tx = tid & 15;      // key-col / d-col group (4 wide)
    const int ty = tid >> 4;      // query-row group (4 wide)
    const int bh = blockIdx.x;
    const int b  = bh >> 4;
    const int h  = bh & 15;
    const int r0 = blockIdx.y * 64;
    const float scale = 0.125f;   // HD^-0.5

    const float* qb = qkv + (size_t)b * N_ * QKV_COLS + h * HD_;

    // Load Q tile transposed (Qs[d][r]), pre-scaled
#pragma unroll
    for (int it = 0; it < 4; ++it) {
        int e = tid + it * 256;          // 0..1023
        int r = e >> 4;                  // 0..63
        int d = (e & 15) << 2;           // 0..60
        float4 v = *(const float4*)(qb + (size_t)(r0 + r) * QKV_COLS + d);
        Qs[(d + 0) * QSS + r] = v.x * scale;
        Qs[(d + 1) * QSS + r] = v.y * scale;
        Qs[(d + 2) * QSS + r] = v.z * scale;
        Qs[(d + 3) * QSS + r] = v.w * scale;
    }

    float mrow[4], lrow[4], o[4][4];
#pragma unroll
    for (int i = 0; i < 4; ++i) {
        mrow[i] = -1e30f; lrow[i] = 0.f;
#pragma unroll
        for (int j = 0; j < 4; ++j) o[i][j] = 0.f;
    }

    for (int t = 0; t < 16; ++t) {
        __syncthreads();   // previous P@V done before overwriting K/V/P tiles

        // Load K (transposed, d-major) and V (m-major) tiles
#pragma unroll
        for (int it = 0; it < 4; ++it) {
            int e = tid + it * 256;
            int m = e >> 4;
            int d = (e & 15) << 2;
            const float* kb = qkv + (size_t)(b * N_ + t * 64 + m) * QKV_COLS
                              + C_ + h * HD_ + d;
            float4 kv = *(const float4*)kb;
            Ks[(d + 0) * QSS + m] = kv.x;
            Ks[(d + 1) * QSS + m] = kv.y;
            Ks[(d + 2) * QSS + m] = kv.z;
            Ks[(d + 3) * QSS + m] = kv.w;
            float4 vv = *(const float4*)(kb + C_);
            *(float4*)&Vs[m * 64 + d] = vv;
        }
        __syncthreads();

        // S = (Q*scale) @ K^T, 4x4 fragment per thread
        float s[4][4];
#pragma unroll
        for (int i = 0; i < 4; ++i)
#pragma unroll
            for (int j = 0; j < 4; ++j) s[i][j] = 0.f;

#pragma unroll 8
        for (int d = 0; d < 64; ++d) {
            float a[4], bb[4];
            *(float4*)a  = *(const float4*)&Qs[d * QSS + ty * 4];
            *(float4*)bb = *(const float4*)&Ks[d * QSS + tx * 4];
#pragma unroll
            for (int i = 0; i < 4; ++i)
#pragma unroll
                for (int j = 0; j < 4; ++j)
                    s[i][j] = fmaf(a[i], bb[j], s[i][j]);
        }

        // Online softmax (row stats reduced across the 16 tx lanes)
#pragma unroll
        for (int i = 0; i < 4; ++i) {
            float rm = fmaxf(fmaxf(s[i][0], s[i][1]), fmaxf(s[i][2], s[i][3]));
#pragma unroll
            for (int off = 8; off >= 1; off >>= 1)
                rm = fmaxf(rm, __shfl_xor_sync(0xffffffffu, rm, off));
            float mnew  = fmaxf(mrow[i], rm);
            float alpha = __expf(mrow[i] - mnew);
            float rs = 0.f;
#pragma unroll
            for (int j = 0; j < 4; ++j) {
                s[i][j] = __expf(s[i][j] - mnew);
                rs += s[i][j];
            }
#pragma unroll
            for (int off = 8; off >= 1; off >>= 1)
                rs += __shfl_xor_sync(0xffffffffu, rs, off);
            lrow[i] = lrow[i] * alpha + rs;
            mrow[i] = mnew;
#pragma unroll
            for (int j = 0; j < 4; ++j) o[i][j] *= alpha;
            *(float4*)&Ps[(ty * 4 + i) * QSS + tx * 4] =
                make_float4(s[i][0], s[i][1], s[i][2], s[i][3]);
        }
        __syncthreads();

        // O += P @ V  (o fragment cols are d-cols tx*4..+3)
#pragma unroll 8
        for (int m = 0; m < 64; ++m) {
            float bb[4];
            *(float4*)bb = *(const float4*)&Vs[m * 64 + tx * 4];
#pragma unroll
            for (int i = 0; i < 4; ++i) {
                float av = Ps[(ty * 4 + i) * QSS + m];
#pragma unroll
                for (int j = 0; j < 4; ++j)
                    o[i][j] = fmaf(av, bb[j], o[i][j]);
            }
        }
    }

    // Epilogue: O / l -> [b, n, h, hd] layout for out-proj
#pragma unroll
    for (int i = 0; i < 4; ++i) {
        float inv = 1.f / lrow[i];
        int r = r0 + ty * 4 + i;
        float4 v = make_float4(o[i][0] * inv, o[i][1] * inv,
                               o[i][2] * inv, o[i][3] * inv);
        *(float4*)(ao + (size_t)(b * N_ + r) * C_ + h * HD_ + tx * 4) = v;
    }
}

// ---------------------------------------------------------------------------
extern "C" void kernel_launch(void* const* d_in, const int* in_sizes, int n_in,
                              void* d_out, int out_size)
{
    const float* x      = (const float*)d_in[0];
    const float* w_qkv  = (const float*)d_in[1];
    const float* w_proj = (const float*)d_in[2];
    const float* b_proj = (const float*)d_in[3];
    float* out = (float*)d_out;

    float *qkv, *ao;
    cudaGetSymbolAddress((void**)&qkv, g_qkv);
    cudaGetSymbolAddress((void**)&ao,  g_ao);

    // 1) QKV projection: [8192,1024] @ [3072,1024]^T
    sgemm_nt<false><<<dim3(QKV_COLS / 128, (B_ * N_) / 128), 256>>>(
        x, w_qkv, nullptr, qkv, B_ * N_, QKV_COLS, C_);

    // 2) Flash attention
    cudaFuncSetAttribute(attn_kernel,
                         cudaFuncAttributeMaxDynamicSharedMemorySize,
                         ATTN_SMEM_BYTES);
    attn_kernel<<<dim3(B_ * H_, N_ / 64), 256, ATTN_SMEM_BYTES>>>(qkv, ao);

    // 3) Output projection + bias: [8192,1024] @ [1024,1024]^T + b
    sgemm_nt<true><<<dim3(C_ / 128, (B_ * N_) / 128), 256>>>(
        ao, w_proj, b_proj, out, B_ * N_, C_, C_);
}